// round 2
// baseline (speedup 1.0000x reference)
#include <cuda_runtime.h>

#define NSd 16
#define NRd 128
#define NTd 4096
#define NROWS (NSd * NRd)
#define NPd 100
#define HPc (1.0f / 99.0f)
#define THREADS 256
#define CHUNK (NTd / THREADS)   // 16

__device__ float g_partials[NROWS];

// deterministic block reduce (fixed tree order)
__device__ __forceinline__ float block_reduce_sum(float v, float* red) {
    int tid = threadIdx.x;
    red[tid] = v;
    __syncthreads();
    #pragma unroll
    for (int s = THREADS / 2; s > 0; s >>= 1) {
        if (tid < s) red[tid] += red[tid + s];
        __syncthreads();
    }
    float r = red[0];
    __syncthreads();
    return r;
}

// deterministic exclusive scan over per-thread values (Hillis-Steele)
__device__ __forceinline__ float block_excl_scan(float v, float* red) {
    int tid = threadIdx.x;
    red[tid] = v;
    __syncthreads();
    #pragma unroll
    for (int off = 1; off < THREADS; off <<= 1) {
        float t = (tid >= off) ? red[tid - off] : 0.0f;
        __syncthreads();
        red[tid] += t;
        __syncthreads();
    }
    float incl = red[tid];
    __syncthreads();
    return incl - v;
}

__global__ __launch_bounds__(THREADS)
void wass_kernel(const float* __restrict__ f,
                 const float* __restrict__ obs,
                 const float* __restrict__ t) {
    __shared__ float buf[NTd];        // row data, then CDF (obs phase, in place)
    __shared__ float red[THREADS];
    __shared__ float sQ[NPd];         // quantile function values
    __shared__ float sR[NPd];         // rhs -> dp (Thomas forward)
    __shared__ float sM[NPd];         // spline second derivatives M[0..99]
    __shared__ float sW[NPd];         // Thomas elimination coeffs (98 used)
    __shared__ float4 coef[NPd];      // packed {a,b,c,d} per segment (99 used)

    const int row = blockIdx.x;
    const int tid = threadIdx.x;
    const int base = tid * CHUNK;
    const float dt = t[1] - t[0];

    // ================= obs phase: build CDF, invert, fit spline =================
    {
        const float4* o4 = (const float4*)(obs + (size_t)row * NTd);
        float lsum = 0.0f;
        for (int k = tid; k < NTd / 4; k += THREADS) {
            float4 v = o4[k];
            float a0 = fabsf(v.x), a1 = fabsf(v.y), a2 = fabsf(v.z), a3 = fabsf(v.w);
            buf[4 * k + 0] = a0; buf[4 * k + 1] = a1;
            buf[4 * k + 2] = a2; buf[4 * k + 3] = a3;
            lsum += a0 + a1 + a2 + a3;
        }
        float total = block_reduce_sum(lsum, red);     // syncs cover buf visibility
        float y0 = buf[0], yl = buf[NTd - 1];
        float inv = 1.0f / (dt * (total - 0.5f * (y0 + yl)));
        float scale = dt * inv;

        // scan pass 1: local sum of g_j = 0.5*(y_j + y_{j+1})
        float ls = 0.0f;
        #pragma unroll
        for (int j = base; j < base + CHUNK; ++j)
            if (j < NTd - 1) ls += 0.5f * (buf[j] + buf[j + 1]);
        float excl = block_excl_scan(ls, red);

        // save the cross-chunk boundary value before in-place overwrite
        float ynext_reg = (tid < THREADS - 1) ? buf[base + CHUNK] : 0.0f;
        __syncthreads();

        // scan pass 2: write CDF F[j] over buf in place
        float cum = excl;
        float ycur = buf[base];
        #pragma unroll
        for (int j = base; j < base + CHUNK; ++j) {
            float yn = (j == base + CHUNK - 1) ? ynext_reg : buf[j + 1];
            buf[j] = cum * scale;
            if (j < NTd - 1) cum += 0.5f * (ycur + yn);
            ycur = yn;
        }
        __syncthreads();
    }

    // ---- inverse CDF at 100 quantiles (jnp.interp semantics) ----
    if (tid < NPd) {
        float p = (tid == NPd - 1) ? 1.0f : tid * HPc;
        float Flast = buf[NTd - 1];
        float q;
        if (p > Flast) {
            q = (NTd - 1) * dt;                 // interp right clamp -> fp[-1]
        } else {
            // searchsorted(F, p, side='right'): first idx with F[idx] > p
            int lo = 0, hi = NTd;
            while (lo < hi) {
                int mid = (lo + hi) >> 1;
                if (buf[mid] <= p) lo = mid + 1; else hi = mid;
            }
            int i = min(max(lo, 1), NTd - 1);
            float F0 = buf[i - 1], F1 = buf[i];
            q = (i - 1) * dt + (p - F0) * dt / (F1 - F0);
        }
        sQ[tid] = q;
    }
    __syncthreads();

    // ---- natural cubic spline: rhs, constant-tridiagonal Thomas solve ----
    if (tid < NPd - 2)
        sR[tid] = 6.0f * (sQ[tid + 2] - 2.0f * sQ[tid + 1] + sQ[tid]) / (HPc * HPc);
    if (tid < NPd - 2)
        sW[tid] = 0.26794919243f;               // w_i limit (2 - sqrt(3))
    __syncthreads();
    if (tid == 0) {
        // exact elimination coeffs; converge to limit within ~8 steps
        float w = 0.25f;
        sW[0] = w;
        for (int i = 1; i < 24; ++i) { w = 1.0f / (4.0f - w); sW[i] = w; }
        // forward sweep
        float dp = sR[0] * sW[0];
        sR[0] = dp;
        for (int i = 1; i < NPd - 2; ++i) { dp = (sR[i] - dp) * sW[i]; sR[i] = dp; }
        // backward sweep -> M[1..98]; natural BCs M[0]=M[99]=0
        float mv = sR[NPd - 3];
        sM[NPd - 2] = mv;
        for (int i = NPd - 4; i >= 0; --i) { mv = sR[i] - sW[i] * mv; sM[i + 1] = mv; }
        sM[0] = 0.0f;
        sM[NPd - 1] = 0.0f;
    }
    __syncthreads();

    // ---- pack per-segment coefficients ----
    if (tid < NPd - 1) {
        float Qj = sQ[tid], Qj1 = sQ[tid + 1];
        float Mj = sM[tid], Mj1 = sM[tid + 1];
        float a = Qj;
        float b = (Qj1 - Qj) / HPc - HPc * (2.0f * Mj + Mj1) / 6.0f;
        float c = Mj * 0.5f;
        float d = (Mj1 - Mj) / (6.0f * HPc);
        coef[tid] = make_float4(a, b, c, d);
    }
    __syncthreads();

    // ================= f phase: renorm, CDF, spline eval, integrate =================
    {
        const float4* f4 = (const float4*)(f + (size_t)row * NTd);
        float lsum = 0.0f;
        for (int k = tid; k < NTd / 4; k += THREADS) {
            float4 v = f4[k];
            float a0 = fabsf(v.x), a1 = fabsf(v.y), a2 = fabsf(v.z), a3 = fabsf(v.w);
            buf[4 * k + 0] = a0; buf[4 * k + 1] = a1;
            buf[4 * k + 2] = a2; buf[4 * k + 3] = a3;
            lsum += a0 + a1 + a2 + a3;
        }
        float total = block_reduce_sum(lsum, red);
        float y0 = buf[0], yl = buf[NTd - 1];
        float inv = 1.0f / (dt * (total - 0.5f * (y0 + yl)));
        float scale = dt * inv;

        float ls = 0.0f;
        #pragma unroll
        for (int j = base; j < base + CHUNK; ++j)
            if (j < NTd - 1) ls += 0.5f * (buf[j] + buf[j + 1]);
        float excl = block_excl_scan(ls, red);

        // fused pass 2: running CDF + spline eval + trapezoid accumulation
        float cum = excl;
        float ycur = buf[base];
        float acc = 0.0f;
        #pragma unroll
        for (int j = base; j < base + CHUNK; ++j) {
            float yn = (j < NTd - 1) ? buf[j + 1] : 0.0f;
            float Fv = cum * scale;
            float xi = fminf(fmaxf(Fv, 0.0f), 99.0f * HPc);
            int idx = (int)(xi * 99.0f);
            idx = min(max(idx, 0), 98);
            float dxv = xi - idx * HPc;
            float4 cf = coef[idx];
            float off = cf.x + dxv * (cf.y + dxv * (cf.z + dxv * cf.w));
            float diff = j * dt - off;
            float w = (j == 0 || j == NTd - 1) ? 0.5f : 1.0f;
            acc += diff * diff * (ycur * inv) * w;
            if (j < NTd - 1) cum += 0.5f * (ycur + yn);
            ycur = yn;
        }
        float rowsum = block_reduce_sum(acc, red);
        if (tid == 0) g_partials[row] = rowsum * dt;
    }
}

__global__ __launch_bounds__(256)
void final_reduce_kernel(float* __restrict__ out) {
    __shared__ double red[256];
    int tid = threadIdx.x;
    double s = 0.0;
    for (int i = tid; i < NROWS; i += 256) s += (double)g_partials[i];
    red[tid] = s;
    __syncthreads();
    #pragma unroll
    for (int st = 128; st > 0; st >>= 1) {
        if (tid < st) red[tid] += red[tid + st];
        __syncthreads();
    }
    if (tid == 0) out[0] = (float)red[0];
}

extern "C" void kernel_launch(void* const* d_in, const int* in_sizes, int n_in,
                              void* d_out, int out_size) {
    const float* f   = (const float*)d_in[0];
    const float* obs = (const float*)d_in[1];
    const float* t   = (const float*)d_in[2];
    wass_kernel<<<NROWS, THREADS>>>(f, obs, t);
    final_reduce_kernel<<<1, 256>>>((float*)d_out);
}

// round 3
// speedup vs baseline: 3.2722x; 3.2722x over previous
#include <cuda_runtime.h>

#define NSd 16
#define NRd 128
#define NTd 4096
#define NROWS (NSd * NRd)
#define NPd 100
#define HPc (1.0f / 99.0f)
#define THREADS 256
#define CHUNK (NTd / THREADS)   // 16
#define IDX(j) ((j) + ((j) >> 4))   // bank-conflict-free skew for stride-16 writers

__device__ float g_partials[NROWS];

struct SharedBlk {
    float sF[NTd + NTd / 16];   // skewed CDF (obs phase only)
    float sFirst[THREADS];      // first element of each thread's chunk
    float sWarp[8];
    float sTot[2];              // [0]=reduce result, [1]=row-last element
    float sQ[NPd];
    float sR[NPd];
    float sM[NPd];
    float sW[NPd];
    float4 coef[NPd];
};

__device__ __forceinline__ float warp_incl_scan(float v) {
    int lane = threadIdx.x & 31;
    #pragma unroll
    for (int o = 1; o < 32; o <<= 1) {
        float tv = __shfl_up_sync(0xffffffffu, v, o);
        if (lane >= o) v += tv;
    }
    return v;
}

// deterministic block-wide exclusive scan (shuffle-based, 3 barriers)
__device__ __forceinline__ float block_excl_scan(float v, SharedBlk* sh) {
    int tid = threadIdx.x, lane = tid & 31, w = tid >> 5;
    __syncthreads();                       // protect sWarp reuse
    float incl = warp_incl_scan(v);
    if (lane == 31) sh->sWarp[w] = incl;
    __syncthreads();
    if (w == 0) {
        float x = (lane < 8) ? sh->sWarp[lane] : 0.0f;
        float xs = warp_incl_scan(x);
        if (lane < 8) sh->sWarp[lane] = xs;
    }
    __syncthreads();
    float off = (w > 0) ? sh->sWarp[w - 1] : 0.0f;
    return off + incl - v;
}

// deterministic block reduce, result broadcast to all threads
__device__ __forceinline__ float block_reduce_bcast(float v, SharedBlk* sh) {
    int tid = threadIdx.x, lane = tid & 31, w = tid >> 5;
    __syncthreads();                       // protect sWarp reuse + order sFirst writes
    #pragma unroll
    for (int o = 16; o > 0; o >>= 1) v += __shfl_down_sync(0xffffffffu, v, o);
    if (lane == 0) sh->sWarp[w] = v;
    __syncthreads();
    if (tid == 0) {
        float s = 0.0f;
        #pragma unroll
        for (int i = 0; i < 8; i++) s += sh->sWarp[i];
        sh->sTot[0] = s;
    }
    __syncthreads();
    return sh->sTot[0];
}

__global__ __launch_bounds__(THREADS)
void wass_kernel(const float* __restrict__ f,
                 const float* __restrict__ obs,
                 const float* __restrict__ t) {
    __shared__ SharedBlk sh;

    const int row = blockIdx.x;
    const int tid = threadIdx.x;
    const int base = tid * CHUNK;
    const float dt = t[1] - t[0];

    float y[CHUNK];

    // ================= obs phase: build CDF, invert, fit spline =================
    {
        const float4* o4 = (const float4*)(obs + (size_t)row * NTd) + tid * 4;
        float lsum = 0.0f;
        #pragma unroll
        for (int q = 0; q < 4; q++) {
            float4 v = o4[q];
            y[4 * q + 0] = fabsf(v.x); y[4 * q + 1] = fabsf(v.y);
            y[4 * q + 2] = fabsf(v.z); y[4 * q + 3] = fabsf(v.w);
            lsum += y[4 * q] + y[4 * q + 1] + y[4 * q + 2] + y[4 * q + 3];
        }
        sh.sFirst[tid] = y[0];
        if (tid == THREADS - 1) sh.sTot[1] = y[CHUNK - 1];
        float total = block_reduce_bcast(lsum, &sh);   // internal barrier orders the writes above
        float y0 = sh.sFirst[0], yl = sh.sTot[1];
        float inv = 1.0f / (dt * (total - 0.5f * (y0 + yl)));
        float scale = dt * inv;
        float ynext = (tid < THREADS - 1) ? sh.sFirst[tid + 1] : 0.0f;

        float ls = 0.0f;
        #pragma unroll
        for (int k = 0; k < CHUNK - 1; ++k) ls += 0.5f * (y[k] + y[k + 1]);
        if (tid < THREADS - 1) ls += 0.5f * (y[CHUNK - 1] + ynext);
        float cum = block_excl_scan(ls, &sh);

        #pragma unroll
        for (int k = 0; k < CHUNK; ++k) {
            sh.sF[IDX(base + k)] = cum * scale;        // conflict-free (skewed)
            float yn = (k < CHUNK - 1) ? y[k + 1] : ynext;
            cum += 0.5f * (y[k] + yn);
        }
        __syncthreads();
    }

    // ---- inverse CDF at 100 quantiles (jnp.interp semantics) ----
    if (tid < NPd) {
        float p = (tid == NPd - 1) ? 1.0f : tid * HPc;
        float Flast = sh.sF[IDX(NTd - 1)];
        float q;
        if (p > Flast) {
            q = (NTd - 1) * dt;
        } else {
            int lo = 0, hi = NTd;                       // searchsorted right
            while (lo < hi) {
                int mid = (lo + hi) >> 1;
                if (sh.sF[IDX(mid)] <= p) lo = mid + 1; else hi = mid;
            }
            int i = min(max(lo, 1), NTd - 1);
            float F0 = sh.sF[IDX(i - 1)], F1 = sh.sF[IDX(i)];
            q = (i - 1) * dt + (p - F0) * dt / (F1 - F0);
        }
        sh.sQ[tid] = q;
    }
    __syncthreads();

    // ---- natural cubic spline: rhs + constant-tridiagonal Thomas ----
    if (tid < NPd - 2) {
        sh.sR[tid] = 6.0f * (sh.sQ[tid + 2] - 2.0f * sh.sQ[tid + 1] + sh.sQ[tid]) / (HPc * HPc);
        sh.sW[tid] = 0.26794919243f;                    // limit 2 - sqrt(3)
    }
    __syncthreads();
    if (tid == 0) {
        float w = 0.25f;
        sh.sW[0] = w;
        for (int i = 1; i < 24; ++i) { w = 1.0f / (4.0f - w); sh.sW[i] = w; }
        float dp = sh.sR[0] * sh.sW[0];
        sh.sR[0] = dp;
        for (int i = 1; i < NPd - 2; ++i) { dp = (sh.sR[i] - dp) * sh.sW[i]; sh.sR[i] = dp; }
        float mv = sh.sR[NPd - 3];
        sh.sM[NPd - 2] = mv;
        for (int i = NPd - 4; i >= 0; --i) { mv = sh.sR[i] - sh.sW[i] * mv; sh.sM[i + 1] = mv; }
        sh.sM[0] = 0.0f;
        sh.sM[NPd - 1] = 0.0f;
    }
    __syncthreads();

    if (tid < NPd - 1) {
        float Qj = sh.sQ[tid], Qj1 = sh.sQ[tid + 1];
        float Mj = sh.sM[tid], Mj1 = sh.sM[tid + 1];
        float a = Qj;
        float b = (Qj1 - Qj) / HPc - HPc * (2.0f * Mj + Mj1) / 6.0f;
        float c = Mj * 0.5f;
        float d = (Mj1 - Mj) / (6.0f * HPc);
        sh.coef[tid] = make_float4(a, b, c, d);
    }
    __syncthreads();

    // ================= f phase: renorm, CDF, spline eval, integrate =================
    {
        const float4* f4 = (const float4*)(f + (size_t)row * NTd) + tid * 4;
        float lsum = 0.0f;
        #pragma unroll
        for (int q = 0; q < 4; q++) {
            float4 v = f4[q];
            y[4 * q + 0] = fabsf(v.x); y[4 * q + 1] = fabsf(v.y);
            y[4 * q + 2] = fabsf(v.z); y[4 * q + 3] = fabsf(v.w);
            lsum += y[4 * q] + y[4 * q + 1] + y[4 * q + 2] + y[4 * q + 3];
        }
        sh.sFirst[tid] = y[0];
        if (tid == THREADS - 1) sh.sTot[1] = y[CHUNK - 1];
        float total = block_reduce_bcast(lsum, &sh);
        float y0 = sh.sFirst[0], yl = sh.sTot[1];
        float inv = 1.0f / (dt * (total - 0.5f * (y0 + yl)));
        float scale = dt * inv;
        float ynext = (tid < THREADS - 1) ? sh.sFirst[tid + 1] : 0.0f;

        float ls = 0.0f;
        #pragma unroll
        for (int k = 0; k < CHUNK - 1; ++k) ls += 0.5f * (y[k] + y[k + 1]);
        if (tid < THREADS - 1) ls += 0.5f * (y[CHUNK - 1] + ynext);
        float cum = block_excl_scan(ls, &sh);

        float acc = 0.0f;
        #pragma unroll
        for (int k = 0; k < CHUNK; ++k) {
            int j = base + k;
            float Fv = cum * scale;
            float xi = fminf(fmaxf(Fv, 0.0f), 1.0f);
            int idx = min(max((int)(xi * 99.0f), 0), 98);
            float dxv = xi - idx * HPc;
            float4 cf = sh.coef[idx];
            float off = cf.x + dxv * (cf.y + dxv * (cf.z + dxv * cf.w));
            float diff = j * dt - off;
            float wgt = (j == 0 || j == NTd - 1) ? 0.5f : 1.0f;
            acc += diff * diff * (y[k] * inv) * wgt;
            float yn = (k < CHUNK - 1) ? y[k + 1] : ynext;
            cum += 0.5f * (y[k] + yn);
        }
        float rowsum = block_reduce_bcast(acc, &sh);
        if (tid == 0) g_partials[row] = rowsum * dt;
    }
}

__global__ __launch_bounds__(1024)
void final_reduce_kernel(float* __restrict__ out) {
    __shared__ double red[32];
    int tid = threadIdx.x, lane = tid & 31, w = tid >> 5;
    double s = 0.0;
    for (int i = tid; i < NROWS; i += 1024) s += (double)g_partials[i];
    #pragma unroll
    for (int o = 16; o > 0; o >>= 1) s += __shfl_down_sync(0xffffffffu, s, o);
    if (lane == 0) red[w] = s;
    __syncthreads();
    if (w == 0) {
        double x = red[lane];
        #pragma unroll
        for (int o = 16; o > 0; o >>= 1) x += __shfl_down_sync(0xffffffffu, x, o);
        if (tid == 0) out[0] = (float)x;
    }
}

extern "C" void kernel_launch(void* const* d_in, const int* in_sizes, int n_in,
                              void* d_out, int out_size) {
    const float* f   = (const float*)d_in[0];
    const float* obs = (const float*)d_in[1];
    const float* t   = (const float*)d_in[2];
    wass_kernel<<<NROWS, THREADS>>>(f, obs, t);
    final_reduce_kernel<<<1, 1024>>>((float*)d_out);
}